// round 8
// baseline (speedup 1.0000x reference)
#include <cuda_runtime.h>
#include <cuda_bf16.h>
#include <math.h>
#include <stdint.h>

// Problem dims
#define Bv 4096
#define Tt 28
#define In 28
#define Hh 512
#define Gg 1536   // 3*H
#define H2 1024   // 2*H

// ---------------- scratch (static device allocations; allowed) ----------------
__device__ float g_gxA[176160768];   // B*T*3H : gx layer0 fwd, reused as gx layer1 fwd
__device__ float g_gxB[176160768];   // B*T*3H : gx layer0 bwd
__device__ float g_h[2 * 2097152];   // 2 * B*H  : layer0 fwd/bwd hidden (fp32 state)
__device__ float g_h1[2097152];      // B*H      : layer1 fwd hidden (fp32 state)
__device__ float g_h1b[2097152];     // B*H      : layer1 bwd hidden (one step)
__device__ float g_gx1b[6291456];    // B*3H     : layer1 bwd gx at t=T-1
__device__ float g_z1[1048576];      // B*256    : fc1 output

// Stacked-K bf16 operands: A' = [Ah|Ah|Al], W' = [Wh|Wl|Wh] so a single GEMM
// over K'=3K computes Ah*Wh + Ah*Wl + Al*Wh (fp32-grade accuracy).
__device__ __nv_bfloat16 g_xs[14680064];     // x stacked  [B*T, 128]
__device__ __nv_bfloat16 g_ws[17694720];     // all weights stacked arena
__device__ __nv_bfloat16 g_y0s[352321536];   // y0 stacked [B*T, 3072]
__device__ __nv_bfloat16 g_hs[2*12582912];   // layer0 h stacked, 2 bufs x 2 dirs x [B,1536]
__device__ __nv_bfloat16 g_h1s[2*6291456];   // layer1 h stacked, 2 bufs x [B,1536]
__device__ __nv_bfloat16 g_lasts[12582912];  // concat(h1f,h1b) stacked [B,3072]

// Weight arena offsets (bf16 elements)
#define WS_IH_L0   0          // 1536 x 128
#define WS_IH_L0R  196608
#define WS_HH_L0   393216     // 1536 x 1536
#define WS_HH_L0R  2752512
#define WS_HH_L1   5111808
#define WS_IH_L1   7471104    // 1536 x 3072
#define WS_IH_L1R  12189696
#define WS_FC1     16908288   // 256 x 3072

// ============================================================================
// PTX helpers (all baseline sm_80+ features; valid on .target sm_103)
// ============================================================================
__device__ __forceinline__ uint32_t smem_u32(const void* p) {
    uint32_t a;
    asm("{ .reg .u64 t; cvta.to.shared.u64 t, %1; cvt.u32.u64 %0, t; }" : "=r"(a) : "l"(p));
    return a;
}
__device__ __forceinline__ void cp16(uint32_t s, const void* g) {
    asm volatile("cp.async.cg.shared.global [%0], [%1], 16;" :: "r"(s), "l"(g));
}
__device__ __forceinline__ void ldsm4(uint32_t* r, uint32_t a) {
    asm volatile("ldmatrix.sync.aligned.m8n8.x4.shared.b16 {%0,%1,%2,%3}, [%4];"
                 : "=r"(r[0]), "=r"(r[1]), "=r"(r[2]), "=r"(r[3]) : "r"(a));
}
__device__ __forceinline__ void mma16816(float* d, const uint32_t* a, uint32_t b0, uint32_t b1) {
    asm volatile("mma.sync.aligned.m16n8k16.row.col.f32.bf16.bf16.f32 "
                 "{%0,%1,%2,%3}, {%4,%5,%6,%7}, {%8,%9}, {%0,%1,%2,%3};"
                 : "+f"(d[0]), "+f"(d[1]), "+f"(d[2]), "+f"(d[3])
                 : "r"(a[0]), "r"(a[1]), "r"(a[2]), "r"(a[3]), "r"(b0), "r"(b1));
}

__device__ __forceinline__ float sigmoidf_(float x) { return 1.f / (1.f + expf(-x)); }
__device__ __forceinline__ void split_bf16(float v, __nv_bfloat16& h, __nv_bfloat16& l) {
    h = __float2bfloat16(v);
    l = __float2bfloat16(v - __bfloat162float(h));
}

// ============================================================================
// Pipelined bf16 GEMM: C = A @ W^T + bias (fp32 accum) — for input projections
// A: [M,K'] bf16 ld=lda. W: [N,K'] bf16 ld=K'. C: fp32 [M,N] ld=ldc.
// 128x128x64 tiles, 3-stage cp.async, swizzled ldmatrix, 8 warps (64x32 each).
// ============================================================================
struct MOp {
    const __nv_bfloat16 *A, *W;
    const float *bias;
    float *C;
};

#define STAGE_B 32768               // A tile 16KB + W tile 16KB
#define SMEM_SZ (3 * STAGE_B)       // 98304

__device__ __forceinline__ void prefetch_stage(const MOp& op, uint32_t sb, int c,
                                               int bm, int bn, int lda, int K, int tid)
{
    const int st = c % 3;
    const uint32_t abase = sb + st * STAGE_B;
    const uint32_t wbase = abase + 16384;
    const int kc0 = c * 64;
#pragma unroll
    for (int i = 0; i < 4; i++) {
        int v = tid + i * 256;          // 0..1023
        int row = v >> 3, ch = v & 7;   // 128 rows x 8 chunks(16B)
        const __nv_bfloat16* g = op.A + (size_t)(bm + row) * lda + kc0 + ch * 8;
        cp16(abase + row * 128 + ((ch ^ (row & 7)) << 4), g);
    }
#pragma unroll
    for (int i = 0; i < 4; i++) {
        int v = tid + i * 256;
        int row = v >> 3, ch = v & 7;
        const __nv_bfloat16* g = op.W + (size_t)(bn + row) * K + kc0 + ch * 8;
        cp16(wbase + row * 128 + ((ch ^ (row & 7)) << 4), g);
    }
    asm volatile("cp.async.commit_group;");
}

__global__ void __launch_bounds__(256, 2) mma_gemm(MOp op0, MOp op1,
                                                   int lda, int ldc, int K)
{
    extern __shared__ char smem[];
    MOp op = (blockIdx.z == 0) ? op0 : op1;
    const uint32_t sb = smem_u32(smem);
    const int tid  = threadIdx.x;
    const int wid  = tid >> 5;
    const int lane = tid & 31;
    const int bm = blockIdx.y * 128;
    const int bn = blockIdx.x * 128;
    const int wm = (wid >> 2) * 64;   // 2 warp rows
    const int wn = (wid & 3) * 32;    // 4 warp cols

    float acc[4][4][4];
#pragma unroll
    for (int i = 0; i < 4; i++)
#pragma unroll
        for (int j = 0; j < 4; j++)
#pragma unroll
            for (int r = 0; r < 4; r++) acc[i][j][r] = 0.f;

    const int nc = K >> 6;

    prefetch_stage(op, sb, 0, bm, bn, lda, K, tid);
    if (nc > 1) prefetch_stage(op, sb, 1, bm, bn, lda, K, tid);

    for (int c = 0; c < nc; c++) {
        if (c + 2 < nc) {
            prefetch_stage(op, sb, c + 2, bm, bn, lda, K, tid);
            asm volatile("cp.async.wait_group 2;");
        } else if (c + 1 < nc) {
            asm volatile("cp.async.wait_group 1;");
        } else {
            asm volatile("cp.async.wait_group 0;");
        }
        __syncthreads();

        const int st = c % 3;
        const uint32_t abase = sb + st * STAGE_B;
        const uint32_t wbase = abase + 16384;

#pragma unroll
        for (int kk = 0; kk < 4; kk++) {   // K=16 steps within BK=64
            uint32_t a[4][4], b[2][4];
#pragma unroll
            for (int mf = 0; mf < 4; mf++) {
                int r   = wm + mf * 16 + ((lane >> 3) & 1) * 8 + (lane & 7);
                int cch = kk * 2 + (lane >> 4);
                ldsm4(a[mf], abase + r * 128 + ((cch ^ (r & 7)) << 4));
            }
#pragma unroll
            for (int nf = 0; nf < 2; nf++) {
                int r   = wn + nf * 16 + ((lane >> 4) & 1) * 8 + (lane & 7);
                int cch = kk * 2 + ((lane >> 3) & 1);
                ldsm4(b[nf], wbase + r * 128 + ((cch ^ (r & 7)) << 4));
            }
#pragma unroll
            for (int mf = 0; mf < 4; mf++)
#pragma unroll
                for (int nt = 0; nt < 4; nt++)
                    mma16816(acc[mf][nt], a[mf],
                             b[nt >> 1][(nt & 1) * 2], b[nt >> 1][(nt & 1) * 2 + 1]);
        }
        __syncthreads();
    }

    // epilogue: bias + fp32 store
#pragma unroll
    for (int mf = 0; mf < 4; mf++) {
        int row = bm + wm + mf * 16 + (lane >> 2);
#pragma unroll
        for (int nt = 0; nt < 4; nt++) {
            int col = bn + wn + nt * 8 + (lane & 3) * 2;
            float b0 = op.bias[col], b1 = op.bias[col + 1];
            float2 v0 = make_float2(acc[mf][nt][0] + b0, acc[mf][nt][1] + b1);
            float2 v1 = make_float2(acc[mf][nt][2] + b0, acc[mf][nt][3] + b1);
            *(float2*)(op.C + (size_t)row * ldc + col) = v0;
            *(float2*)(op.C + (size_t)(row + 8) * ldc + col) = v1;
        }
    }
}

// ============================================================================
// Fused recurrent step: gh = h_stacked @ Whh'^T, then GRU gate, all in one.
// CTA: 64 batch rows x 128 h-cols, computes r/z/n gates (12 warps, 4/gate).
// Stacked h is double-buffered (read s.hs, write s.hs_out) to avoid races.
// ============================================================================
struct RStep {
    const __nv_bfloat16 *hs;     // stacked h input  [B,1536]
    const __nv_bfloat16 *Ws;     // stacked Whh      [1536,1536]
    const float *bhh;            // [1536]
    const float *gx;             // [B,T,1536]
    float *h;                    // fp32 hidden      [B,512] (in/out)
    __nv_bfloat16 *hs_out;       // stacked h output [B,1536]
    __nv_bfloat16 *y0s;          // [B,T,3072] or nullptr
    int t;                       // time index into gx / y0s
    int y0off;                   // dir*512 column offset in y0
};

#define FS_STAGE 57344               // A 8KB + 3x W 16KB
#define FS_SMEM  (3 * FS_STAGE)      // 172032

__device__ __forceinline__ void fs_prefetch(const RStep& s, uint32_t sb, int c,
                                            int bm, int bj, int tid)
{
    const int st = c % 3;
    const uint32_t base = sb + st * FS_STAGE;
    const int kc0 = c * 64;
    for (int i = tid; i < 3584; i += 384) {
        uint32_t dst;
        const __nv_bfloat16* src;
        if (i < 512) {                      // A: 64 rows x 8 chunks
            int row = i >> 3, ch = i & 7;
            src = s.hs + (size_t)(bm + row) * Gg + kc0 + ch * 8;
            dst = base + row * 128 + ((ch ^ (row & 7)) << 4);
        } else {                            // W: 3 gates x 128 rows x 8 chunks
            int v = i - 512;
            int gg = v >> 10, r = (v >> 3) & 127, ch = v & 7;
            src = s.Ws + (size_t)((gg << 9) + bj * 128 + r) * Gg + kc0 + ch * 8;
            dst = base + 8192 + gg * 16384 + r * 128 + ((ch ^ (r & 7)) << 4);
        }
        cp16(dst, src);
    }
    asm volatile("cp.async.commit_group;");
}

__global__ void __launch_bounds__(384, 1) fused_step(RStep s0, RStep s1)
{
    extern __shared__ char smem[];
    RStep s = (blockIdx.z == 0) ? s0 : s1;
    const uint32_t sb = smem_u32(smem);
    const int tid  = threadIdx.x;
    const int wid  = tid >> 5;
    const int lane = tid & 31;
    const int bj = blockIdx.x;          // 0..3 over H
    const int bm = blockIdx.y * 64;     // batch tile
    const int g    = wid >> 2;          // gate 0..2
    const int widx = wid & 3;
    const int wr = widx >> 1;           // 0..1 (32-row half)
    const int wc = widx & 1;            // 0..1 (64-col half)

    float acc[2][8][4];
#pragma unroll
    for (int i = 0; i < 2; i++)
#pragma unroll
        for (int j = 0; j < 8; j++)
#pragma unroll
            for (int r = 0; r < 4; r++) acc[i][j][r] = 0.f;

    const int nc = Gg / 64;   // 24

    fs_prefetch(s, sb, 0, bm, bj, tid);
    fs_prefetch(s, sb, 1, bm, bj, tid);

    for (int c = 0; c < nc; c++) {
        if (c + 2 < nc) {
            fs_prefetch(s, sb, c + 2, bm, bj, tid);
            asm volatile("cp.async.wait_group 2;");
        } else if (c + 1 < nc) {
            asm volatile("cp.async.wait_group 1;");
        } else {
            asm volatile("cp.async.wait_group 0;");
        }
        __syncthreads();

        const int st = c % 3;
        const uint32_t abase = sb + st * FS_STAGE;
        const uint32_t wbase = abase + 8192 + g * 16384;

#pragma unroll
        for (int kk = 0; kk < 4; kk++) {
            uint32_t a[2][4], b[4][4];
#pragma unroll
            for (int mf = 0; mf < 2; mf++) {
                int r   = wr * 32 + mf * 16 + ((lane >> 3) & 1) * 8 + (lane & 7);
                int cch = kk * 2 + (lane >> 4);
                ldsm4(a[mf], abase + r * 128 + ((cch ^ (r & 7)) << 4));
            }
#pragma unroll
            for (int nf = 0; nf < 4; nf++) {
                int r   = wc * 64 + nf * 16 + ((lane >> 4) & 1) * 8 + (lane & 7);
                int cch = kk * 2 + ((lane >> 3) & 1);
                ldsm4(b[nf], wbase + r * 128 + ((cch ^ (r & 7)) << 4));
            }
#pragma unroll
            for (int mf = 0; mf < 2; mf++)
#pragma unroll
                for (int nt = 0; nt < 8; nt++)
                    mma16816(acc[mf][nt], a[mf],
                             b[nt >> 1][(nt & 1) * 2], b[nt >> 1][(nt & 1) * 2 + 1]);
        }
        __syncthreads();
    }

    // stage fragments to smem (reuse pipeline buffers): 3 x 64 x 128 fp32
    float* sacc = (float*)smem;
    float* sg   = sacc + g * 8192;
#pragma unroll
    for (int mf = 0; mf < 2; mf++) {
        int row0 = wr * 32 + mf * 16 + (lane >> 2);
#pragma unroll
        for (int nt = 0; nt < 8; nt++) {
            int col = wc * 64 + nt * 8 + (lane & 3) * 2;
            sg[row0 * 128 + col]           = acc[mf][nt][0];
            sg[row0 * 128 + col + 1]       = acc[mf][nt][1];
            sg[(row0 + 8) * 128 + col]     = acc[mf][nt][2];
            sg[(row0 + 8) * 128 + col + 1] = acc[mf][nt][3];
        }
    }
    __syncthreads();

    // gate math
    for (int idx = tid; idx < 8192; idx += 384) {
        const int row = idx >> 7;
        const int j   = idx & 127;
        const int bgl = bm + row;
        const int jg  = bj * 128 + j;

        float ar = sacc[idx];
        float az = sacc[8192 + idx];
        float an = sacc[16384 + idx];

        const float* gxr = s.gx + ((size_t)bgl * Tt + s.t) * Gg;
        float r = sigmoidf_(gxr[jg] + ar + s.bhh[jg]);
        float z = sigmoidf_(gxr[512 + jg] + az + s.bhh[512 + jg]);
        float n = tanhf(gxr[1024 + jg] + r * (an + s.bhh[1024 + jg]));

        const size_t hidx = (size_t)bgl * Hh + jg;
        float hn = (1.f - z) * n + z * s.h[hidx];
        s.h[hidx] = hn;

        __nv_bfloat16 hh, hl;
        split_bf16(hn, hh, hl);
        __nv_bfloat16* ho = s.hs_out + (size_t)bgl * Gg;
        ho[jg] = hh;  ho[512 + jg] = hh;  ho[1024 + jg] = hl;

        if (s.y0s) {
            const size_t yrow = ((size_t)bgl * Tt + s.t) * 3072;
            const int c = s.y0off + jg;
            s.y0s[yrow + c]        = hh;
            s.y0s[yrow + 1024 + c] = hh;
            s.y0s[yrow + 2048 + c] = hl;
        }
    }
}

// ============================================================================
// small kernels
// ============================================================================
__global__ void zero_f32(float* p, int n)
{
    int i = blockIdx.x * blockDim.x + threadIdx.x;
    if (i < n) p[i] = 0.f;
}
__global__ void zero_bf16(__nv_bfloat16* p, int n)
{
    int i = blockIdx.x * blockDim.x + threadIdx.x;
    if (i < n) p[i] = __float2bfloat16(0.f);
}

// fp32 [rows,K] -> stacked bf16 [rows, Kp*nseg]; per-seg mode: 0=hi, 1=lo, 2=zero
__global__ void convert_stack(const float* __restrict__ src, __nv_bfloat16* __restrict__ dst,
                              int K, int Kp, int nseg, int modes, int total)
{
    int i = blockIdx.x * blockDim.x + threadIdx.x;
    if (i >= total) return;
    int Kt  = Kp * nseg;
    int row = i / Kt;
    int rem = i - row * Kt;
    int seg = rem / Kp;
    int kk  = rem - seg * Kp;
    int mode = (modes >> (2 * seg)) & 3;
    float v = (mode != 2 && kk < K) ? src[(size_t)row * K + kk] : 0.f;
    __nv_bfloat16 h = __float2bfloat16(v);
    __nv_bfloat16 o = h;
    if (mode == 1) o = __float2bfloat16(v - __bfloat162float(h));
    dst[i] = o;
}

// Layer-1 backward: output at original t=T-1 is the FIRST reversed step (h0=0).
__global__ void gate_l1b_last(const float* __restrict__ bhh)
{
    const int idx = blockIdx.x * blockDim.x + threadIdx.x;
    const int b = idx >> 9;
    const int j = idx & 511;
    const float* gx = g_gx1b + (size_t)b * Gg;
    float r = sigmoidf_(gx[j] + bhh[j]);
    float z = sigmoidf_(gx[Hh + j] + bhh[Hh + j]);
    float n = tanhf(gx[2 * Hh + j] + r * bhh[2 * Hh + j]);
    g_h1b[(size_t)b * Hh + j] = (1.f - z) * n;
}

__global__ void concat_last(void)
{
    const int idx = blockIdx.x * blockDim.x + threadIdx.x;  // B*2H
    const int b = idx >> 10;
    const int j = idx & 1023;
    float v = (j < Hh) ? g_h1[(size_t)b * Hh + j] : g_h1b[(size_t)b * Hh + (j - Hh)];
    __nv_bfloat16 hh, hl;
    split_bf16(v, hh, hl);
    __nv_bfloat16* ls = g_lasts + (size_t)b * 3072;
    ls[j] = hh; ls[1024 + j] = hh; ls[2048 + j] = hl;
}

// BN + ReLU + fc2 + log_softmax
__global__ void head_kernel(const float* __restrict__ gamma, const float* __restrict__ beta,
                            const float* __restrict__ mean, const float* __restrict__ var,
                            const float* __restrict__ fc2w, const float* __restrict__ fc2b,
                            float* __restrict__ out)
{
    const int b = blockIdx.x;
    const int tid = threadIdx.x;
    __shared__ float a[256];
    __shared__ float logits[10];

    float v = g_z1[(size_t)b * 256 + tid];
    v = (v - mean[tid]) * rsqrtf(var[tid] + 1e-5f) * gamma[tid] + beta[tid];
    a[tid] = fmaxf(v, 0.f);
    __syncthreads();

    if (tid < 10) {
        float acc = fc2b[tid];
        const float* wrow = fc2w + tid * 256;
        for (int k = 0; k < 256; k++) acc = fmaf(a[k], wrow[k], acc);
        logits[tid] = acc;
    }
    __syncthreads();

    if (tid == 0) {
        float mx = logits[0];
        for (int i = 1; i < 10; i++) mx = fmaxf(mx, logits[i]);
        float s = 0.f;
        for (int i = 0; i < 10; i++) s += expf(logits[i] - mx);
        float lse = mx + logf(s);
        for (int i = 0; i < 10; i++) out[(size_t)b * 10 + i] = logits[i] - lse;
    }
}

// ============================================================================
// host-side launch
// ============================================================================
extern "C" void kernel_launch(void* const* d_in, const int* in_sizes, int n_in,
                              void* d_out, int out_size)
{
    (void)in_sizes; (void)n_in; (void)out_size;
    const float* x         = (const float*)d_in[0];
    const float* W_ih_l0   = (const float*)d_in[1];
    const float* W_hh_l0   = (const float*)d_in[2];
    const float* b_ih_l0   = (const float*)d_in[3];
    const float* b_hh_l0   = (const float*)d_in[4];
    const float* W_ih_l0r  = (const float*)d_in[5];
    const float* W_hh_l0r  = (const float*)d_in[6];
    const float* b_ih_l0r  = (const float*)d_in[7];
    const float* b_hh_l0r  = (const float*)d_in[8];
    const float* W_ih_l1   = (const float*)d_in[9];
    const float* W_hh_l1   = (const float*)d_in[10];
    const float* b_ih_l1   = (const float*)d_in[11];
    const float* b_hh_l1   = (const float*)d_in[12];
    const float* W_ih_l1r  = (const float*)d_in[13];
    const float* W_hh_l1r  = (const float*)d_in[14];
    const float* b_ih_l1r  = (const float*)d_in[15];
    const float* b_hh_l1r  = (const float*)d_in[16];
    const float* fc1_w     = (const float*)d_in[17];
    const float* fc1_b     = (const float*)d_in[18];
    const float* bn_gamma  = (const float*)d_in[19];
    const float* bn_beta   = (const float*)d_in[20];
    const float* bn_mean   = (const float*)d_in[21];
    const float* bn_var    = (const float*)d_in[22];
    const float* fc2_w     = (const float*)d_in[23];
    const float* fc2_b     = (const float*)d_in[24];
    float* out = (float*)d_out;

    float *p_gxA, *p_gxB, *p_h, *p_h1, *p_gx1b, *p_z1;
    __nv_bfloat16 *p_xs, *p_ws, *p_y0s, *p_hs, *p_h1s, *p_ls;
    cudaGetSymbolAddress((void**)&p_gxA,  g_gxA);
    cudaGetSymbolAddress((void**)&p_gxB,  g_gxB);
    cudaGetSymbolAddress((void**)&p_h,    g_h);
    cudaGetSymbolAddress((void**)&p_h1,   g_h1);
    cudaGetSymbolAddress((void**)&p_gx1b, g_gx1b);
    cudaGetSymbolAddress((void**)&p_z1,   g_z1);
    cudaGetSymbolAddress((void**)&p_xs,   g_xs);
    cudaGetSymbolAddress((void**)&p_ws,   g_ws);
    cudaGetSymbolAddress((void**)&p_y0s,  g_y0s);
    cudaGetSymbolAddress((void**)&p_hs,   g_hs);
    cudaGetSymbolAddress((void**)&p_h1s,  g_h1s);
    cudaGetSymbolAddress((void**)&p_ls,   g_lasts);

    cudaFuncSetAttribute(mma_gemm, cudaFuncAttributeMaxDynamicSharedMemorySize, SMEM_SZ);
    cudaFuncSetAttribute(fused_step, cudaFuncAttributeMaxDynamicSharedMemorySize, FS_SMEM);

    const int BH = Bv * Hh;      // 2,097,152
    const int BG = Bv * Gg;      // 6,291,456
    const int MT = Bv * Tt;      // 114,688

    // seg-mode packs: 0=hi, 1=lo, 2=zero (2 bits per segment)
    const int MODES_A4 = 0 | (0 << 2) | (1 << 4) | (2 << 6);  // [hi|hi|lo|0]
    const int MODES_W4 = 0 | (1 << 2) | (0 << 4) | (2 << 6);  // [hi|lo|hi|0]
    const int MODES_W3 = 0 | (1 << 2) | (0 << 4);             // [hi|lo|hi]

    // 0) stack inputs/weights
    {
        int tot = MT * 128;
        convert_stack<<<(tot + 255) / 256, 256>>>(x, p_xs, In, 32, 4, MODES_A4, tot);
        struct { const float* s; int off, K, Kp, nseg, modes, rows; } cv[8] = {
            { W_ih_l0,  WS_IH_L0,  28,   32,   4, MODES_W4, 1536 },
            { W_ih_l0r, WS_IH_L0R, 28,   32,   4, MODES_W4, 1536 },
            { W_hh_l0,  WS_HH_L0,  512,  512,  3, MODES_W3, 1536 },
            { W_hh_l0r, WS_HH_L0R, 512,  512,  3, MODES_W3, 1536 },
            { W_hh_l1,  WS_HH_L1,  512,  512,  3, MODES_W3, 1536 },
            { W_ih_l1,  WS_IH_L1,  1024, 1024, 3, MODES_W3, 1536 },
            { W_ih_l1r, WS_IH_L1R, 1024, 1024, 3, MODES_W3, 1536 },
            { fc1_w,    WS_FC1,    1024, 1024, 3, MODES_W3, 256  },
        };
        for (int i = 0; i < 8; i++) {
            int t = cv[i].rows * cv[i].Kp * cv[i].nseg;
            convert_stack<<<(t + 255) / 256, 256>>>(cv[i].s, p_ws + cv[i].off,
                                                    cv[i].K, cv[i].Kp, cv[i].nseg,
                                                    cv[i].modes, t);
        }
    }

    // 1) zero states (fp32 + stacked buffer 0)
    zero_f32<<<(2 * BH + 255) / 256, 256>>>(p_h, 2 * BH);
    zero_f32<<<(BH + 255) / 256, 256>>>(p_h1, BH);
    zero_bf16<<<(2 * BG + 255) / 256, 256>>>(p_hs, 2 * BG);
    zero_bf16<<<(BG + 255) / 256, 256>>>(p_h1s, BG);

    // 2) layer-0 input projections (fwd+bwd), K'=128
    {
        MOp f{ p_xs, p_ws + WS_IH_L0,  b_ih_l0,  p_gxA };
        MOp r{ p_xs, p_ws + WS_IH_L0R, b_ih_l0r, p_gxB };
        mma_gemm<<<dim3(Gg / 128, MT / 128, 2), 256, SMEM_SZ>>>(f, r, 128, Gg, 128);
    }

    // 3) layer-0 recurrence: fused GEMM+gate, fwd+bwd per launch, double-buffered hs
    for (int s = 0; s < Tt; s++) {
        const int cur = s & 1;
        RStep f{ p_hs + (size_t)cur * 2 * BG,
                 p_ws + WS_HH_L0,  b_hh_l0,  p_gxA, p_h,
                 p_hs + (size_t)(cur ^ 1) * 2 * BG,
                 p_y0s, s, 0 };
        RStep r{ p_hs + (size_t)cur * 2 * BG + BG,
                 p_ws + WS_HH_L0R, b_hh_l0r, p_gxB, p_h + BH,
                 p_hs + (size_t)(cur ^ 1) * 2 * BG + BG,
                 p_y0s, Tt - 1 - s, 512 };
        fused_step<<<dim3(4, Bv / 64, 2), 384, FS_SMEM>>>(f, r);
    }

    // 4) layer-1 input projection (fwd, all t), K'=3072 — reuses g_gxA
    {
        MOp f{ p_y0s, p_ws + WS_IH_L1, b_ih_l1, p_gxA };
        mma_gemm<<<dim3(Gg / 128, MT / 128, 1), 256, SMEM_SZ>>>(f, f, 3072, Gg, 3072);
    }

    // 5) layer-1 bwd input projection at t=T-1 only
    {
        MOp f{ p_y0s + (size_t)(Tt - 1) * 3072, p_ws + WS_IH_L1R, b_ih_l1r, p_gx1b };
        mma_gemm<<<dim3(Gg / 128, Bv / 128, 1), 256, SMEM_SZ>>>(f, f, Tt * 3072, Gg, 3072);
    }
    gate_l1b_last<<<BH / 256, 256>>>(b_hh_l1r);

    // 6) layer-1 fwd recurrence: fused
    for (int s = 0; s < Tt; s++) {
        const int cur = s & 1;
        RStep f{ p_h1s + (size_t)cur * BG,
                 p_ws + WS_HH_L1, b_hh_l1, p_gxA, p_h1,
                 p_h1s + (size_t)(cur ^ 1) * BG,
                 nullptr, s, 0 };
        fused_step<<<dim3(4, Bv / 64, 1), 384, FS_SMEM>>>(f, f);
    }

    // 7) head
    concat_last<<<(Bv * H2) / 256, 256>>>();
    {
        MOp f{ p_ls, p_ws + WS_FC1, fc1_b, p_z1 };
        mma_gemm<<<dim3(256 / 128, Bv / 128, 1), 256, SMEM_SZ>>>(f, f, 3072, 256, 3072);
    }
    head_kernel<<<Bv, 256>>>(bn_gamma, bn_beta, bn_mean, bn_var, fc2_w, fc2_b, out);
}

// round 11
// speedup vs baseline: 1.6383x; 1.6383x over previous
#include <cuda_runtime.h>
#include <cuda_bf16.h>
#include <math.h>
#include <stdint.h>

// Problem dims
#define Bv 4096
#define Tt 28
#define In 28
#define Hh 512
#define Gg 1536   // 3*H
#define H2 1024   // 2*H

#define BH 2097152      // B*H
#define BG 6291456      // B*3H
#define MT 114688       // B*T

// ---------------- scratch (static device allocations; allowed) ----------------
__device__ float g_gxA[176160768];   // B*T*3H : gx layer0 fwd, reused as gx layer1 fwd
__device__ float g_gxB[176160768];   // B*T*3H : gx layer0 bwd
__device__ float g_gh[2 * 6291456];  // L0: [dir][B,1536]; L1: [gh | gh2] split-K halves
__device__ float g_h[2 * 2097152];   // layer0 fwd/bwd hidden (fp32 state)
__device__ float g_h1[2097152];      // layer1 fwd hidden (fp32 state)
__device__ float g_h1b[2097152];     // layer1 bwd hidden (one step)
__device__ float g_gx1b[6291456];    // layer1 bwd gx at t=T-1
__device__ float g_z1[1048576];      // B*256 fc1 output
__device__ float g_zb[1536];         // zero bias

// bf16 operands. A-side stores hi+lo only; the GEMM synthesizes [hi|hi|lo]
// (virtual stacking). W-side stays physically stacked [Wh|Wl|Wh].
__device__ __nv_bfloat16 g_xs[14680064];     // x stacked [B*T,128]  [hi|hi|lo|0] physical
__device__ __nv_bfloat16 g_ws[17694720];     // weights arena (stacked)
__device__ __nv_bfloat16 g_y0h[117440512];   // y0 hi [B*T,1024]
__device__ __nv_bfloat16 g_y0l[117440512];   // y0 lo [B*T,1024]
__device__ __nv_bfloat16 g_hh[2*2*2097152];  // l0 h hi, [buf][dir][B,512]
__device__ __nv_bfloat16 g_hl[2*2*2097152];  // l0 h lo
__device__ __nv_bfloat16 g_h1h[2*2097152];   // l1 h hi, [buf][B,512]
__device__ __nv_bfloat16 g_h1l[2*2097152];   // l1 h lo
__device__ __nv_bfloat16 g_lasth[4194304];   // concat hi [B,1024]
__device__ __nv_bfloat16 g_lastl[4194304];   // concat lo [B,1024]

// Weight arena offsets (bf16 elements)
#define WS_IH_L0   0          // 1536 x 128
#define WS_IH_L0R  196608
#define WS_HH_L0   393216     // 1536 x 1536
#define WS_HH_L0R  2752512
#define WS_HH_L1   5111808
#define WS_IH_L1   7471104    // 1536 x 3072
#define WS_IH_L1R  12189696
#define WS_FC1     16908288   // 256 x 3072

// ============================================================================
// PTX helpers (baseline sm_80+ features; valid on .target sm_103)
// ============================================================================
__device__ __forceinline__ uint32_t smem_u32(const void* p) {
    uint32_t a;
    asm("{ .reg .u64 t; cvta.to.shared.u64 t, %1; cvt.u32.u64 %0, t; }" : "=r"(a) : "l"(p));
    return a;
}
__device__ __forceinline__ void cp16(uint32_t s, const void* g) {
    asm volatile("cp.async.cg.shared.global [%0], [%1], 16;" :: "r"(s), "l"(g));
}
__device__ __forceinline__ void ldsm4(uint32_t* r, uint32_t a) {
    asm volatile("ldmatrix.sync.aligned.m8n8.x4.shared.b16 {%0,%1,%2,%3}, [%4];"
                 : "=r"(r[0]), "=r"(r[1]), "=r"(r[2]), "=r"(r[3]) : "r"(a));
}
__device__ __forceinline__ void mma16816(float* d, const uint32_t* a, uint32_t b0, uint32_t b1) {
    asm volatile("mma.sync.aligned.m16n8k16.row.col.f32.bf16.bf16.f32 "
                 "{%0,%1,%2,%3}, {%4,%5,%6,%7}, {%8,%9}, {%0,%1,%2,%3};"
                 : "+f"(d[0]), "+f"(d[1]), "+f"(d[2]), "+f"(d[3])
                 : "r"(a[0]), "r"(a[1]), "r"(a[2]), "r"(a[3]), "r"(b0), "r"(b1));
}

__device__ __forceinline__ float sigmoidf_(float x) { return 1.f / (1.f + expf(-x)); }
__device__ __forceinline__ void split_bf16(float v, __nv_bfloat16& h, __nv_bfloat16& l) {
    h = __float2bfloat16(v);
    l = __float2bfloat16(v - __bfloat162float(h));
}

// ============================================================================
// Pipelined bf16 GEMM: C = A' @ W'^T + bias (fp32 accum), virtual-stacked A.
// A' column k maps to: seg = k>>kshift; seg<2 -> Ahi[k & mask], seg2 -> Alo.
// (physical A: kshift=30 so seg==0 always and k indexes Ahi directly)
// W: [N, ldw] physically stacked, offset by koff via pre-offset pointer.
// 128x128x64 tiles, 3-stage cp.async, swizzled ldmatrix, 8 warps (64x32 each).
// ============================================================================
struct MOp {
    const __nv_bfloat16 *Ahi, *Alo;  // hi / lo A arrays (row stride lda each)
    const __nv_bfloat16 *W;          // stacked weights (pre-offset for split-K)
    const float *bias;
    float *C;
    int lda;
    int koff;                        // split-K offset into virtual A columns
};

#define STAGE_B 32768               // A tile 16KB + W tile 16KB
#define SMEM_SZ (3 * STAGE_B)       // 98304

__device__ __forceinline__ void prefetch_stage(const MOp& op, uint32_t sb, int c,
                                               int bm, int bn, int ldw,
                                               int kshift, int kmask, int tid)
{
    const int st = c % 3;
    const uint32_t abase = sb + st * STAGE_B;
    const uint32_t wbase = abase + 16384;
    const int kc0 = c * 64;
#pragma unroll
    for (int i = 0; i < 4; i++) {
        int v = tid + i * 256;          // 0..1023
        int row = v >> 3, ch = v & 7;   // 128 rows x 8 chunks(16B)
        int kg  = op.koff + kc0 + ch * 8;
        int seg = kg >> kshift;
        int off = kg & kmask;
        const __nv_bfloat16* g = (seg < 2 ? op.Ahi : op.Alo)
                               + (size_t)(bm + row) * op.lda + off;
        cp16(abase + row * 128 + ((ch ^ (row & 7)) << 4), g);
    }
#pragma unroll
    for (int i = 0; i < 4; i++) {
        int v = tid + i * 256;
        int row = v >> 3, ch = v & 7;
        const __nv_bfloat16* g = op.W + (size_t)(bn + row) * ldw + kc0 + ch * 8;
        cp16(wbase + row * 128 + ((ch ^ (row & 7)) << 4), g);
    }
    asm volatile("cp.async.commit_group;");
}

__global__ void __launch_bounds__(256, 2) mma_gemm(MOp op0, MOp op1,
                                                   int ldw, int ldc, int K, int kshift)
{
    extern __shared__ char smem[];
    MOp op = (blockIdx.z == 0) ? op0 : op1;
    const uint32_t sb = smem_u32(smem);
    const int kmask = (kshift >= 30) ? 0x3FFFFFFF : ((1 << kshift) - 1);
    const int tid  = threadIdx.x;
    const int wid  = tid >> 5;
    const int lane = tid & 31;
    const int bm = blockIdx.y * 128;
    const int bn = blockIdx.x * 128;
    const int wm = (wid >> 2) * 64;   // 2 warp rows
    const int wn = (wid & 3) * 32;    // 4 warp cols

    float acc[4][4][4];
#pragma unroll
    for (int i = 0; i < 4; i++)
#pragma unroll
        for (int j = 0; j < 4; j++)
#pragma unroll
            for (int r = 0; r < 4; r++) acc[i][j][r] = 0.f;

    const int nc = K >> 6;

    prefetch_stage(op, sb, 0, bm, bn, ldw, kshift, kmask, tid);
    if (nc > 1) prefetch_stage(op, sb, 1, bm, bn, ldw, kshift, kmask, tid);

    for (int c = 0; c < nc; c++) {
        if (c + 2 < nc) {
            prefetch_stage(op, sb, c + 2, bm, bn, ldw, kshift, kmask, tid);
            asm volatile("cp.async.wait_group 2;");
        } else if (c + 1 < nc) {
            asm volatile("cp.async.wait_group 1;");
        } else {
            asm volatile("cp.async.wait_group 0;");
        }
        __syncthreads();

        const int st = c % 3;
        const uint32_t abase = sb + st * STAGE_B;
        const uint32_t wbase = abase + 16384;

#pragma unroll
        for (int kk = 0; kk < 4; kk++) {   // K=16 steps within BK=64
            uint32_t a[4][4], b[2][4];
#pragma unroll
            for (int mf = 0; mf < 4; mf++) {
                int r   = wm + mf * 16 + ((lane >> 3) & 1) * 8 + (lane & 7);
                int cch = kk * 2 + (lane >> 4);
                ldsm4(a[mf], abase + r * 128 + ((cch ^ (r & 7)) << 4));
            }
#pragma unroll
            for (int nf = 0; nf < 2; nf++) {
                int r   = wn + nf * 16 + ((lane >> 4) & 1) * 8 + (lane & 7);
                int cch = kk * 2 + ((lane >> 3) & 1);
                ldsm4(b[nf], wbase + r * 128 + ((cch ^ (r & 7)) << 4));
            }
#pragma unroll
            for (int mf = 0; mf < 4; mf++)
#pragma unroll
                for (int nt = 0; nt < 4; nt++)
                    mma16816(acc[mf][nt], a[mf],
                             b[nt >> 1][(nt & 1) * 2], b[nt >> 1][(nt & 1) * 2 + 1]);
        }
        __syncthreads();
    }

    // epilogue: bias + fp32 store
#pragma unroll
    for (int mf = 0; mf < 4; mf++) {
        int row = bm + wm + mf * 16 + (lane >> 2);
#pragma unroll
        for (int nt = 0; nt < 4; nt++) {
            int col = bn + wn + nt * 8 + (lane & 3) * 2;
            float b0 = op.bias[col], b1 = op.bias[col + 1];
            float2 v0 = make_float2(acc[mf][nt][0] + b0, acc[mf][nt][1] + b1);
            float2 v1 = make_float2(acc[mf][nt][2] + b0, acc[mf][nt][3] + b1);
            *(float2*)(op.C + (size_t)row * ldc + col) = v0;
            *(float2*)(op.C + (size_t)(row + 8) * ldc + col) = v1;
        }
    }
}

// ============================================================================
// init: zero all state in one launch
// f32: g_h (2BH), g_h1 (BH), g_zb (1536); bf16: hh/hl buf0 (2BH each),
// h1h/h1l buf0 (BH each)
// ============================================================================
#define ZF1 (2 * BH)
#define ZF2 (ZF1 + BH)
#define ZF3 (ZF2 + 1536)
#define ZB1 (2 * BH)
#define ZB2 (ZB1 + 2 * BH)
#define ZB3 (ZB2 + BH)
#define ZB4 (ZB3 + BH)
#define ZTOT (ZF3 + ZB4)

__global__ void zero_all(void)
{
    long long i = (long long)blockIdx.x * blockDim.x + threadIdx.x;
    if (i >= ZTOT) return;
    if (i < ZF3) {
        if (i < ZF1)      g_h[i] = 0.f;
        else if (i < ZF2) g_h1[i - ZF1] = 0.f;
        else              g_zb[i - ZF2] = 0.f;
    } else {
        long long k = i - ZF3;
        __nv_bfloat16 z = __float2bfloat16(0.f);
        if (k < ZB1)      g_hh[k] = z;
        else if (k < ZB2) g_hl[k - ZB1] = z;
        else if (k < ZB3) g_h1h[k - ZB2] = z;
        else              g_h1l[k - ZB3] = z;
    }
}

// ============================================================================
// conversion: all hi/lo stacking jobs in one launch (block-offset job table)
// per-seg mode: 0=hi, 1=lo, 2=zero
// ============================================================================
struct CvJobs {
    const float* src[9];
    __nv_bfloat16* dst[9];
    int off[10];          // cumulative block offsets
    int K[9], Kp[9], modes[9], total[9];
};

__global__ void convert_all(CvJobs jobs)
{
    int bid = blockIdx.x;
    int ji = 0;
#pragma unroll
    for (int t = 1; t < 9; t++) ji += (bid >= jobs.off[t]);
    int i = (bid - jobs.off[ji]) * 256 + threadIdx.x;
    if (i >= jobs.total[ji]) return;
    const float* src = jobs.src[ji];
    int K = jobs.K[ji], Kp = jobs.Kp[ji], modes = jobs.modes[ji];

    int row = i / (Kp == 32 ? 128 : (Kp == 512 ? 1536 : 3072));
    int rem = i - row * (Kp == 32 ? 128 : (Kp == 512 ? 1536 : 3072));
    int seg = rem / Kp;
    int kk  = rem - seg * Kp;
    int mode = (modes >> (2 * seg)) & 3;
    float v = (mode != 2 && kk < K) ? src[(size_t)row * K + kk] : 0.f;
    __nv_bfloat16 h = __float2bfloat16(v);
    __nv_bfloat16 o = h;
    if (mode == 1) o = __float2bfloat16(v - __bfloat162float(h));
    jobs.dst[ji][i] = o;
}

// ============================================================================
// gate kernels
// ============================================================================
// Layer-0 gating, both directions (blockIdx.y = dir). fp32 state + hi/lo writes.
__global__ void gru_gate_l0(int s, int cur)
{
    const int idx = blockIdx.x * blockDim.x + threadIdx.x;  // over B*H
    const int dir = blockIdx.y;
    const int b = idx >> 9;
    const int j = idx & 511;
    const int t = (dir == 0) ? s : (Tt - 1 - s);

    const float* gx = (dir == 0 ? g_gxA : g_gxB) + ((size_t)b * Tt + t) * Gg;
    const float* gh = g_gh + (size_t)dir * BG + (size_t)b * Gg;
    const size_t hidx = (size_t)dir * BH + (size_t)b * Hh + j;

    float r = sigmoidf_(gx[j] + gh[j]);
    float z = sigmoidf_(gx[Hh + j] + gh[Hh + j]);
    float n = tanhf(gx[2 * Hh + j] + r * gh[2 * Hh + j]);
    float hn = (1.f - z) * n + z * g_h[hidx];
    g_h[hidx] = hn;

    __nv_bfloat16 hh, hl;
    split_bf16(hn, hh, hl);
    const size_t mo = (size_t)(cur ^ 1) * 2 * BH + hidx;
    g_hh[mo] = hh;  g_hl[mo] = hl;
    const size_t yi = ((size_t)b * Tt + t) * 1024 + (size_t)dir * Hh + j;
    g_y0h[yi] = hh; g_y0l[yi] = hl;
}

// Layer-1 gating: gh comes in two split-K halves summed here.
__global__ void gru_gate_l1(int s, int cur)
{
    const int idx = blockIdx.x * blockDim.x + threadIdx.x;
    const int b = idx >> 9;
    const int j = idx & 511;

    const float* gx  = g_gxA + ((size_t)b * Tt + s) * Gg;
    const float* gh  = g_gh + (size_t)b * Gg;
    const float* gh2 = g_gh + (size_t)BG + (size_t)b * Gg;
    const size_t hidx = (size_t)b * Hh + j;

    float ar = gh[j] + gh2[j];
    float az = gh[Hh + j] + gh2[Hh + j];
    float an = gh[2 * Hh + j] + gh2[2 * Hh + j];
    float r = sigmoidf_(gx[j] + ar);
    float z = sigmoidf_(gx[Hh + j] + az);
    float n = tanhf(gx[2 * Hh + j] + r * an);
    float hn = (1.f - z) * n + z * g_h1[hidx];
    g_h1[hidx] = hn;

    __nv_bfloat16 hh, hl;
    split_bf16(hn, hh, hl);
    const size_t mo = (size_t)(cur ^ 1) * BH + hidx;
    g_h1h[mo] = hh;  g_h1l[mo] = hl;
}

// Layer-1 backward: output at original t=T-1 is the FIRST reversed step (h0=0).
__global__ void gate_l1b_last(const float* __restrict__ bhh)
{
    const int idx = blockIdx.x * blockDim.x + threadIdx.x;
    const int b = idx >> 9;
    const int j = idx & 511;
    const float* gx = g_gx1b + (size_t)b * Gg;
    float r = sigmoidf_(gx[j] + bhh[j]);
    float z = sigmoidf_(gx[Hh + j] + bhh[Hh + j]);
    float n = tanhf(gx[2 * Hh + j] + r * bhh[2 * Hh + j]);
    g_h1b[(size_t)b * Hh + j] = (1.f - z) * n;
}

__global__ void concat_last(void)
{
    const int idx = blockIdx.x * blockDim.x + threadIdx.x;  // B*2H
    const int b = idx >> 10;
    const int j = idx & 1023;
    float v = (j < Hh) ? g_h1[(size_t)b * Hh + j] : g_h1b[(size_t)b * Hh + (j - Hh)];
    __nv_bfloat16 hh, hl;
    split_bf16(v, hh, hl);
    g_lasth[(size_t)b * H2 + j] = hh;
    g_lastl[(size_t)b * H2 + j] = hl;
}

// BN + ReLU + fc2 + log_softmax
__global__ void head_kernel(const float* __restrict__ gamma, const float* __restrict__ beta,
                            const float* __restrict__ mean, const float* __restrict__ var,
                            const float* __restrict__ fc2w, const float* __restrict__ fc2b,
                            float* __restrict__ out)
{
    const int b = blockIdx.x;
    const int tid = threadIdx.x;
    __shared__ float a[256];
    __shared__ float logits[10];

    float v = g_z1[(size_t)b * 256 + tid];
    v = (v - mean[tid]) * rsqrtf(var[tid] + 1e-5f) * gamma[tid] + beta[tid];
    a[tid] = fmaxf(v, 0.f);
    __syncthreads();

    if (tid < 10) {
        float acc = fc2b[tid];
        const float* wrow = fc2w + tid * 256;
        for (int k = 0; k < 256; k++) acc = fmaf(a[k], wrow[k], acc);
        logits[tid] = acc;
    }
    __syncthreads();

    if (tid == 0) {
        float mx = logits[0];
        for (int i = 1; i < 10; i++) mx = fmaxf(mx, logits[i]);
        float s = 0.f;
        for (int i = 0; i < 10; i++) s += expf(logits[i] - mx);
        float lse = mx + logf(s);
        for (int i = 0; i < 10; i++) out[(size_t)b * 10 + i] = logits[i] - lse;
    }
}

// ============================================================================
// host-side launch
// ============================================================================
extern "C" void kernel_launch(void* const* d_in, const int* in_sizes, int n_in,
                              void* d_out, int out_size)
{
    (void)in_sizes; (void)n_in; (void)out_size;
    const float* x         = (const float*)d_in[0];
    const float* W_ih_l0   = (const float*)d_in[1];
    const float* W_hh_l0   = (const float*)d_in[2];
    const float* b_ih_l0   = (const float*)d_in[3];
    const float* b_hh_l0   = (const float*)d_in[4];
    const float* W_ih_l0r  = (const float*)d_in[5];
    const float* W_hh_l0r  = (const float*)d_in[6];
    const float* b_ih_l0r  = (const float*)d_in[7];
    const float* b_hh_l0r  = (const float*)d_in[8];
    const float* W_ih_l1   = (const float*)d_in[9];
    const float* W_hh_l1   = (const float*)d_in[10];
    const float* b_ih_l1   = (const float*)d_in[11];
    const float* b_hh_l1   = (const float*)d_in[12];
    const float* W_ih_l1r  = (const float*)d_in[13];
    const float* W_hh_l1r  = (const float*)d_in[14];
    const float* b_ih_l1r  = (const float*)d_in[15];
    const float* b_hh_l1r  = (const float*)d_in[16];
    const float* fc1_w     = (const float*)d_in[17];
    const float* fc1_b     = (const float*)d_in[18];
    const float* bn_gamma  = (const float*)d_in[19];
    const float* bn_beta   = (const float*)d_in[20];
    const float* bn_mean   = (const float*)d_in[21];
    const float* bn_var    = (const float*)d_in[22];
    const float* fc2_w     = (const float*)d_in[23];
    const float* fc2_b     = (const float*)d_in[24];
    float* out = (float*)d_out;

    float *p_gxA, *p_gxB, *p_gh, *p_gx1b, *p_z1, *p_zb;
    __nv_bfloat16 *p_xs, *p_ws, *p_y0h, *p_y0l, *p_hh, *p_hl, *p_h1h, *p_h1l, *p_lh, *p_ll;
    cudaGetSymbolAddress((void**)&p_gxA,  g_gxA);
    cudaGetSymbolAddress((void**)&p_gxB,  g_gxB);
    cudaGetSymbolAddress((void**)&p_gh,   g_gh);
    cudaGetSymbolAddress((void**)&p_gx1b, g_gx1b);
    cudaGetSymbolAddress((void**)&p_z1,   g_z1);
    cudaGetSymbolAddress((void**)&p_zb,   g_zb);
    cudaGetSymbolAddress((void**)&p_xs,   g_xs);
    cudaGetSymbolAddress((void**)&p_ws,   g_ws);
    cudaGetSymbolAddress((void**)&p_y0h,  g_y0h);
    cudaGetSymbolAddress((void**)&p_y0l,  g_y0l);
    cudaGetSymbolAddress((void**)&p_hh,   g_hh);
    cudaGetSymbolAddress((void**)&p_hl,   g_hl);
    cudaGetSymbolAddress((void**)&p_h1h,  g_h1h);
    cudaGetSymbolAddress((void**)&p_h1l,  g_h1l);
    cudaGetSymbolAddress((void**)&p_lh,   g_lasth);
    cudaGetSymbolAddress((void**)&p_ll,   g_lastl);

    cudaFuncSetAttribute(mma_gemm, cudaFuncAttributeMaxDynamicSharedMemorySize, SMEM_SZ);

    // seg-mode packs: 0=hi, 1=lo, 2=zero (2 bits per segment)
    const int MODES_A4 = 0 | (0 << 2) | (1 << 4) | (2 << 6);  // [hi|hi|lo|0]
    const int MODES_W4 = 0 | (1 << 2) | (0 << 4) | (2 << 6);  // [hi|lo|hi|0]
    const int MODES_W3 = 0 | (1 << 2) | (0 << 4);             // [hi|lo|hi]

    // 0) conversions (one launch) + zero init (one launch)
    {
        CvJobs cj;
        const float* srcs[9] = { x, W_ih_l0, W_ih_l0r, W_hh_l0, W_hh_l0r,
                                 W_hh_l1, W_ih_l1, W_ih_l1r, fc1_w };
        __nv_bfloat16* dsts[9] = { p_xs, p_ws + WS_IH_L0, p_ws + WS_IH_L0R,
                                   p_ws + WS_HH_L0, p_ws + WS_HH_L0R, p_ws + WS_HH_L1,
                                   p_ws + WS_IH_L1, p_ws + WS_IH_L1R, p_ws + WS_FC1 };
        int Ks[9]  = { 28, 28, 28, 512, 512, 512, 1024, 1024, 1024 };
        int Kps[9] = { 32, 32, 32, 512, 512, 512, 1024, 1024, 1024 };
        int mds[9] = { MODES_A4, MODES_W4, MODES_W4, MODES_W3, MODES_W3,
                       MODES_W3, MODES_W3, MODES_W3, MODES_W3 };
        int tots[9] = { MT * 128, 1536 * 128, 1536 * 128, 1536 * 1536, 1536 * 1536,
                        1536 * 1536, 1536 * 3072, 1536 * 3072, 256 * 3072 };
        int off = 0;
        for (int i = 0; i < 9; i++) {
            cj.src[i] = srcs[i]; cj.dst[i] = dsts[i];
            cj.K[i] = Ks[i]; cj.Kp[i] = Kps[i]; cj.modes[i] = mds[i]; cj.total[i] = tots[i];
            cj.off[i] = off;
            off += (tots[i] + 255) / 256;
        }
        cj.off[9] = off;
        convert_all<<<off, 256>>>(cj);
        zero_all<<<(ZTOT + 255) / 256, 256>>>();
    }

    // 1) layer-0 input projections (fwd+bwd), physical stacked xs, K'=128
    {
        MOp f{ p_xs, p_xs, p_ws + WS_IH_L0,  b_ih_l0,  p_gxA, 128, 0 };
        MOp r{ p_xs, p_xs, p_ws + WS_IH_L0R, b_ih_l0r, p_gxB, 128, 0 };
        mma_gemm<<<dim3(Gg / 128, MT / 128, 2), 256, SMEM_SZ>>>(f, r, 128, Gg, 128, 30);
    }

    // 2) layer-0 recurrence: GEMM (virtual [hi|hi|lo], K'=1536) + gate, per step
    for (int s = 0; s < Tt; s++) {
        const int cur = s & 1;
        const size_t mb = (size_t)cur * 2 * BH;
        MOp f{ p_hh + mb,      p_hl + mb,      p_ws + WS_HH_L0,  b_hh_l0,  p_gh,      512, 0 };
        MOp r{ p_hh + mb + BH, p_hl + mb + BH, p_ws + WS_HH_L0R, b_hh_l0r, p_gh + BG, 512, 0 };
        mma_gemm<<<dim3(Gg / 128, Bv / 128, 2), 256, SMEM_SZ>>>(f, r, Gg, Gg, Gg, 9);
        gru_gate_l0<<<dim3(BH / 256, 2), 256>>>(s, cur);
    }

    // 3) layer-1 input projection (fwd, all t), virtual y0 [hi|hi|lo], K'=3072
    {
        MOp f{ p_y0h, p_y0l, p_ws + WS_IH_L1, b_ih_l1, p_gxA, 1024, 0 };
        mma_gemm<<<dim3(Gg / 128, MT / 128, 1), 256, SMEM_SZ>>>(f, f, 3072, Gg, 3072, 10);
    }

    // 4) layer-1 bwd input projection at t=T-1 only
    {
        MOp f{ p_y0h + (size_t)(Tt - 1) * 1024, p_y0l + (size_t)(Tt - 1) * 1024,
               p_ws + WS_IH_L1R, b_ih_l1r, p_gx1b, Tt * 1024, 0 };
        mma_gemm<<<dim3(Gg / 128, Bv / 128, 1), 256, SMEM_SZ>>>(f, f, 3072, Gg, 3072, 10);
    }
    gate_l1b_last<<<BH / 256, 256>>>(b_hh_l1r);

    // 5) layer-1 fwd recurrence: split-K (two 768-halves) to fix wave quantization
    for (int s = 0; s < Tt; s++) {
        const int cur = s & 1;
        const size_t mb = (size_t)cur * BH;
        MOp h0{ p_h1h + mb, p_h1l + mb, p_ws + WS_HH_L1,       b_hh_l1, p_gh,      512, 0 };
        MOp h1{ p_h1h + mb, p_h1l + mb, p_ws + WS_HH_L1 + 768, p_zb,    p_gh + BG, 512, 768 };
        mma_gemm<<<dim3(Gg / 128, Bv / 128, 2), 256, SMEM_SZ>>>(h0, h1, Gg, Gg, 768, 9);
        gru_gate_l1<<<BH / 256, 256>>>(s, cur);
    }

    // 6) head
    concat_last<<<(Bv * H2) / 256, 256>>>();
    {
        MOp f{ p_lh, p_ll, p_ws + WS_FC1, fc1_b, p_z1, 1024, 0 };
        mma_gemm<<<dim3(256 / 128, Bv / 128, 1), 256, SMEM_SZ>>>(f, f, 3072, 256, 3072, 10);
    }
    head_kernel<<<Bv, 256>>>(bn_gamma, bn_beta, bn_mean, bn_var, fc2_w, fc2_b, out);
}